// round 15
// baseline (speedup 1.0000x reference)
#include <cuda_runtime.h>
#include <cuda_fp16.h>
#include <stdint.h>
#include <math.h>

#define B_SZ 4
#define T_LEN 1024
#define E_LEN 1024
#define S_LEN 2048
#define D_DIM 2048
#define H_DIM 256
#define N_HEADS 16
#define K_HEADS 8

__device__ __half g_kraw[(size_t)B_SZ * S_LEN * K_HEADS * H_DIM];
__device__ __half g_q16[(size_t)B_SZ * T_LEN * N_HEADS * H_DIM];
__device__ __half g_k16[(size_t)B_SZ * S_LEN * K_HEADS * H_DIM];
__device__ __half g_v16[(size_t)B_SZ * S_LEN * K_HEADS * H_DIM];
__device__ __half g_hs2 [(size_t)4096 * 2048];
__device__ __half g_enc2[(size_t)4096 * 2048];
__device__ __half g_qw2 [(size_t)4096 * 2048];
__device__ __half g_kw2 [(size_t)2048 * 2048];
__device__ __half g_vw2 [(size_t)2048 * 2048];
__device__ __half g_ow2 [(size_t)2048 * 4096];
__device__ __half g_at2 [(size_t)4096 * 4096];   // Q-raw scratch, then flash out / O-GEMM in

// ---------------- helpers ----------------
__device__ __forceinline__ uint32_t smem_u32(const void* p) {
    uint32_t a;
    asm("{ .reg .u64 t; cvta.to.shared.u64 t, %1; cvt.u32.u64 %0, t; }" : "=r"(a) : "l"(p));
    return a;
}
#define CP16(dst, src) \
    asm volatile("cp.async.cg.shared.global [%0], [%1], 16;" :: "r"(dst), "l"(src) : "memory")
#define CP_COMMIT asm volatile("cp.async.commit_group;" ::: "memory")
#define CP_WAIT2  asm volatile("cp.async.wait_group 2;" ::: "memory")
#define CP_WAIT1  asm volatile("cp.async.wait_group 1;" ::: "memory")
#define CP_WAIT0  asm volatile("cp.async.wait_group 0;" ::: "memory")
#define LDSM4(r0, r1, r2, r3, addr) \
    asm volatile("ldmatrix.sync.aligned.m8n8.x4.shared.b16 {%0,%1,%2,%3}, [%4];" \
        : "=r"(r0), "=r"(r1), "=r"(r2), "=r"(r3) : "r"(addr))
#define LDSM4T(r0, r1, r2, r3, addr) \
    asm volatile("ldmatrix.sync.aligned.m8n8.x4.trans.shared.b16 {%0,%1,%2,%3}, [%4];" \
        : "=r"(r0), "=r"(r1), "=r"(r2), "=r"(r3) : "r"(addr))
#define MMAH16816(d, a, b0, b1) \
    asm volatile("mma.sync.aligned.m16n8k16.row.col.f32.f16.f16.f32 " \
        "{%0,%1,%2,%3}, {%4,%5,%6,%7}, {%8,%9}, {%0,%1,%2,%3};" \
        : "+f"((d)[0]), "+f"((d)[1]), "+f"((d)[2]), "+f"((d)[3]) \
        : "r"((a)[0]), "r"((a)[1]), "r"((a)[2]), "r"((a)[3]), "r"(b0), "r"(b1))

__device__ __forceinline__ uint32_t gsw(int row, int kchunk) {
    return (uint32_t)(row * 128 + ((kchunk ^ (row & 7)) << 4));
}
__device__ __forceinline__ uint32_t fsw(int row, int kbyte) {
    return (uint32_t)(row * 512 + ((((kbyte >> 4) ^ (row & 7))) << 4) + (kbyte & 15));
}
__device__ __forceinline__ uint32_t packh2(float a, float b) {
    __half2 h = __floats2half2_rn(a, b);
    return *(uint32_t*)&h;
}

// ---------------- convert kernels ----------------
__global__ __launch_bounds__(256) void a2h_kernel(
    const float* __restrict__ X, __half* __restrict__ Y)
{
    size_t idx = ((size_t)blockIdx.x * 256 + threadIdx.x) * 4;
    float4 v = *(const float4*)(X + idx);
    __half2 h0 = __floats2half2_rn(v.x, v.y);
    __half2 h1 = __floats2half2_rn(v.z, v.w);
    *(uint2*)(Y + idx) = make_uint2(*(uint32_t*)&h0, *(uint32_t*)&h1);
}

__global__ __launch_bounds__(256) void wsplit_kernel(
    const float* __restrict__ W, __half* __restrict__ Yt,
    int Kd, int cph, long long hstr, int krs)
{
    __shared__ float t[32][33];
    int k0 = blockIdx.y * 32, j0 = blockIdx.x * 32;
    int tx = threadIdx.x & 31, ty8 = threadIdx.x >> 5;
#pragma unroll
    for (int i = 0; i < 4; i++) {
        int kl = ty8 + i * 8;
        int j = j0 + tx;
        t[kl][tx] = W[(size_t)(j / cph) * hstr + (size_t)(k0 + kl) * krs + (j % cph)];
    }
    __syncthreads();
#pragma unroll
    for (int i = 0; i < 4; i++) {
        int j = j0 + ty8 + i * 8;
        int k = k0 + tx;
        Yt[(size_t)j * Kd + k] = __float2half(t[tx][ty8 + i * 8]);
    }
}

// ---------------- HMMA fp16 GEMM (R14, unchanged) ----------------
#define GSTAGES 3
#define STG_BYTES 32768
#define GEMM_SMEM (GSTAGES * STG_BYTES)

__global__ void __launch_bounds__(128, 2) gemm_hmma(
    const __half* __restrict__ A, const __half* __restrict__ Bw,
    void* __restrict__ Cv, int Kp, int Mpb, long long outBS, int rowOff, int ldc,
    int outHalf, int mGT, int mGS, int mOff)
{
    extern __shared__ char smraw[];
    const uint32_t sb = smem_u32(smraw);
    const int tid = threadIdx.x;
    const int lane = tid & 31, wid = tid >> 5;
    const int wm = wid & 1, wn = wid >> 1;
    const int m0 = (blockIdx.y / mGT) * mGS + (blockIdx.y % mGT) * 128 + mOff;
    const int n0 = blockIdx.x * 128;
    const int nIter = Kp >> 6;

    const int crow = tid >> 3;
    const int ckc = tid & 7;
    const uint32_t csw = gsw(crow, ckc);
    const __half* ga = A + (size_t)(m0 + crow) * Kp + ckc * 8;
    const __half* gb = Bw + (size_t)(n0 + crow) * Kp + ckc * 8;

    const int r8 = lane & 7, sel = lane >> 3;
    uint32_t aRB[4]; int aRX[4];
    const int dselA = sel >> 1;
#pragma unroll
    for (int mf = 0; mf < 4; mf++) {
        int row = wm * 64 + mf * 16 + r8 + ((sel & 1) << 3);
        aRB[mf] = (uint32_t)(row * 128);
        aRX[mf] = row & 7;
    }
    uint32_t bRB[4]; int bRX[4];
    const int dselB = sel & 1;
#pragma unroll
    for (int np = 0; np < 4; np++) {
        int row = wn * 64 + np * 16 + r8 + ((sel >> 1) << 3);
        bRB[np] = 16384u + (uint32_t)(row * 128);
        bRX[np] = row & 7;
    }

    float acc[4][8][4];
#pragma unroll
    for (int mf = 0; mf < 4; mf++)
#pragma unroll
        for (int nf = 0; nf < 8; nf++)
#pragma unroll
            for (int q = 0; q < 4; q++) acc[mf][nf][q] = 0.f;

#pragma unroll
    for (int s = 0; s < 2; s++) {
        uint32_t base = sb + (uint32_t)s * STG_BYTES;
        const __half* pa = ga + s * 64;
        const __half* pb = gb + s * 64;
#pragma unroll
        for (int p = 0; p < 8; p++) {
            uint32_t so = csw + (uint32_t)p * 2048u;
            CP16(base + so, pa + (size_t)p * 16 * Kp);
            CP16(base + 16384u + so, pb + (size_t)p * 16 * Kp);
        }
        CP_COMMIT;
    }

    for (int it = 0; it < nIter; it++) {
        if (it + 2 < nIter) {
            int s = (it + 2) % GSTAGES;
            uint32_t base = sb + (uint32_t)s * STG_BYTES;
            const __half* pa = ga + (size_t)(it + 2) * 64;
            const __half* pb = gb + (size_t)(it + 2) * 64;
#pragma unroll
            for (int p = 0; p < 8; p++) {
                uint32_t so = csw + (uint32_t)p * 2048u;
                CP16(base + so, pa + (size_t)p * 16 * Kp);
                CP16(base + 16384u + so, pb + (size_t)p * 16 * Kp);
            }
        }
        CP_COMMIT;
        CP_WAIT2;
        __syncthreads();

        uint32_t sbase = sb + (uint32_t)(it % GSTAGES) * STG_BYTES;
#pragma unroll
        for (int ks = 0; ks < 4; ks++) {
            uint32_t af[4][4];
#pragma unroll
            for (int mf = 0; mf < 4; mf++)
                LDSM4(af[mf][0], af[mf][1], af[mf][2], af[mf][3],
                      sbase + aRB[mf] + (uint32_t)((((ks << 1) + dselA) ^ aRX[mf]) << 4));
            uint32_t bf[4][4];
#pragma unroll
            for (int np = 0; np < 4; np++)
                LDSM4(bf[np][0], bf[np][1], bf[np][2], bf[np][3],
                      sbase + bRB[np] + (uint32_t)((((ks << 1) + dselB) ^ bRX[np]) << 4));
#pragma unroll
            for (int mf = 0; mf < 4; mf++)
#pragma unroll
                for (int np = 0; np < 4; np++) {
                    MMAH16816(acc[mf][np * 2 + 0], af[mf], bf[np][0], bf[np][1]);
                    MMAH16816(acc[mf][np * 2 + 1], af[mf], bf[np][2], bf[np][3]);
                }
        }
        __syncthreads();
    }

#pragma unroll
    for (int mf = 0; mf < 4; mf++)
#pragma unroll
        for (int rh = 0; rh < 2; rh++) {
            int gr = m0 + wm * 64 + mf * 16 + (lane >> 2) + rh * 8;
            int bi = gr / Mpb;
            int rr = gr - bi * Mpb;
            size_t base = (size_t)bi * outBS + (size_t)(rr + rowOff) * ldc
                        + n0 + wn * 64 + (lane & 3) * 2;
            if (outHalf) {
                __half* rowp = (__half*)Cv + base;
#pragma unroll
                for (int nf = 0; nf < 8; nf++) {
                    __half2 v = __floats2half2_rn(acc[mf][nf][rh * 2 + 0], acc[mf][nf][rh * 2 + 1]);
                    *(__half2*)(rowp + nf * 8) = v;
                }
            } else {
                float* rowp = (float*)Cv + base;
#pragma unroll
                for (int nf = 0; nf < 8; nf++) {
                    float2 v = make_float2(acc[mf][nf][rh * 2 + 0], acc[mf][nf][rh * 2 + 1]);
                    *(float2*)(rowp + nf * 8) = v;
                }
            }
        }
}

// ---------------- RMS-norm (+RoPE) fp16 -> fp16, warp-per-row ----------------
__global__ __launch_bounds__(256) void rms_rope_w_kernel(
    const __half* __restrict__ buf, __half* __restrict__ outh,
    const float* __restrict__ scale,
    int heads, int rowsPerBatch, int bufRPB, int rowStart, int doRope, float outScale)
{
    int rowIdx = blockIdx.x * 8 + (threadIdx.x >> 5);
    int lane = threadIdx.x & 31;
    int head = rowIdx % heads;
    int tmp = rowIdx / heads;
    int t = tmp % rowsPerBatch;
    int b = tmp / rowsPerBatch;
    size_t off = ((size_t)((size_t)b * bufRPB + rowStart + t) * heads + head) * H_DIM;

    uint2 u1 = *(const uint2*)(buf + off + lane * 4);
    uint2 u2 = *(const uint2*)(buf + off + 128 + lane * 4);
    float2 fa = __half22float2(*(__half2*)&u1.x);
    float2 fb = __half22float2(*(__half2*)&u1.y);
    float2 fc = __half22float2(*(__half2*)&u2.x);
    float2 fd = __half22float2(*(__half2*)&u2.y);
    float x1[4] = { fa.x, fa.y, fb.x, fb.y };
    float x2[4] = { fc.x, fc.y, fd.x, fd.y };
    float ss = x1[0]*x1[0] + x1[1]*x1[1] + x1[2]*x1[2] + x1[3]*x1[3]
             + x2[0]*x2[0] + x2[1]*x2[1] + x2[2]*x2[2] + x2[3]*x2[3];
#pragma unroll
    for (int o = 16; o > 0; o >>= 1) ss += __shfl_xor_sync(0xffffffffu, ss, o);
    float rinv = rsqrtf(ss * (1.f / 256.f) + 1e-6f) * outScale;

    float4 s1 = *(const float4*)(scale + lane * 4);
    float4 s2 = *(const float4*)(scale + 128 + lane * 4);
    float sa1[4] = { s1.x, s1.y, s1.z, s1.w };
    float sa2[4] = { s2.x, s2.y, s2.z, s2.w };
    float y1[4], y2[4], o1[4], o2[4];
#pragma unroll
    for (int i = 0; i < 4; i++) {
        y1[i] = x1[i] * rinv * (1.f + sa1[i]);
        y2[i] = x2[i] * rinv * (1.f + sa2[i]);
    }
    if (doRope) {
#pragma unroll
        for (int i = 0; i < 4; i++) {
            float ang = (float)t * exp2f(-(float)(lane * 4 + i) * 0.10381025296522988f);
            float sn, cs;
            sincosf(ang, &sn, &cs);
            o1[i] = y1[i] * cs - y2[i] * sn;
            o2[i] = y2[i] * cs + y1[i] * sn;
        }
    } else {
#pragma unroll
        for (int i = 0; i < 4; i++) { o1[i] = y1[i]; o2[i] = y2[i]; }
    }
    __half2 a0 = __floats2half2_rn(o1[0], o1[1]);
    __half2 a1 = __floats2half2_rn(o1[2], o1[3]);
    __half2 b0 = __floats2half2_rn(o2[0], o2[1]);
    __half2 b1 = __floats2half2_rn(o2[2], o2[3]);
    *(uint2*)(outh + off + lane * 4) = make_uint2(*(uint32_t*)&a0, *(uint32_t*)&a1);
    *(uint2*)(outh + off + 128 + lane * 4) = make_uint2(*(uint32_t*)&b0, *(uint32_t*)&b1);
}

// ---------------- flash v3 (unchanged R14) ----------------
#define F2_KB 65536u
#define F2_VB 131072u
#define F2_ST 32768u
#define FH2_SMEM 196608

__global__ void __launch_bounds__(256, 1) flash2_hmma(
    const __half* __restrict__ Qh, const __half* __restrict__ Kh,
    const __half* __restrict__ Vh, __half* __restrict__ Oh, int qt0)
{
    extern __shared__ char smraw[];
    const uint32_t sb = smem_u32(smraw);
    const int tid = threadIdx.x, lane = tid & 31, w = tid >> 5;
    const int qt = blockIdx.x + qt0, n = blockIdx.y, b = blockIdx.z;
    const int kh = n >> 1, qbase = qt << 7;

    const char* qg = (const char*)(Qh + ((size_t)(b * T_LEN + qbase) * N_HEADS + n) * H_DIM);
#pragma unroll
    for (int p = 0; p < 16; p++) {
        int idx = tid + p * 256;
        int r = idx >> 5, c = idx & 31;
        CP16(sb + fsw(r, c * 16), qg + (size_t)r * (N_HEADS * H_DIM * 2) + c * 16);
    }
    CP_COMMIT;

    const char* kg = (const char*)(Kh + ((size_t)b * S_LEN * K_HEADS + kh) * H_DIM);
    const char* vg = (const char*)(Vh + ((size_t)b * S_LEN * K_HEADS + kh) * H_DIM);
    const int kvstride = K_HEADS * H_DIM * 2;

    const int nSelf = (qt + 1) << 1;
    const int nT = nSelf + (E_LEN >> 6);

#pragma unroll
    for (int p = 0; p < 8; p++) {
        int idx = tid + p * 256;
        int r = idx >> 5, c = idx & 31;
        uint32_t sw = fsw(r, c * 16);
        CP16(sb + F2_KB + sw, kg + (size_t)r * kvstride + c * 16);
        CP16(sb + F2_VB + sw, vg + (size_t)r * kvstride + c * 16);
    }
    CP_COMMIT;

    float oacc[32][4];
#pragma unroll
    for (int nf = 0; nf < 32; nf++)
#pragma unroll
        for (int q = 0; q < 4; q++) oacc[nf][q] = 0.f;
    float m1 = -INFINITY, m2 = -INFINITY, l1 = 0.f, l2 = 0.f;

    const int r8 = lane & 7, sel = lane >> 3;
    const int rowA = w * 16 + r8 + ((sel & 1) << 3);
    const int dselA = sel >> 1;
    const int dselB = sel & 1;
    const int r1g = w * 16 + (lane >> 2), r2g = r1g + 8;
    const uint32_t aBaseQ = sb + (uint32_t)rowA * 512u;
    const int rowAx = rowA & 7;

    for (int t = 0; t < nT; t++) {
        if (t + 1 < nT) {
            int s0n = (t + 1 < nSelf) ? ((t + 1) << 6) : (T_LEN + ((t + 1 - nSelf) << 6));
            uint32_t kb = sb + F2_KB + (uint32_t)((t + 1) & 1) * F2_ST;
            uint32_t vb = sb + F2_VB + (uint32_t)((t + 1) & 1) * F2_ST;
#pragma unroll
            for (int p = 0; p < 8; p++) {
                int idx = tid + p * 256;
                int r = idx >> 5, c = idx & 31;
                uint32_t sw = fsw(r, c * 16);
                CP16(kb + sw, kg + (size_t)(s0n + r) * kvstride + c * 16);
                CP16(vb + sw, vg + (size_t)(s0n + r) * kvstride + c * 16);
            }
            CP_COMMIT;
            CP_WAIT1;
        } else {
            CP_WAIT0;
        }
        __syncthreads();

        const int s0 = (t < nSelf) ? (t << 6) : (T_LEN + ((t - nSelf) << 6));
        const bool diag = (t >= nSelf - 2) && (t < nSelf);
        const uint32_t sK = sb + F2_KB + (uint32_t)(t & 1) * F2_ST;
        const uint32_t sV = sb + F2_VB + (uint32_t)(t & 1) * F2_ST;

        float sacc[8][4];
#pragma unroll
        for (int nf = 0; nf < 8; nf++)
#pragma unroll
            for (int q = 0; q < 4; q++) sacc[nf][q] = 0.f;
#pragma unroll 4
        for (int ks = 0; ks < 16; ks++) {
            uint32_t a[4];
            LDSM4(a[0], a[1], a[2], a[3], aBaseQ + (uint32_t)((((ks << 1) + dselA) ^ rowAx) << 4));
#pragma unroll
            for (int nf2 = 0; nf2 < 4; nf2++) {
                int rowB = nf2 * 16 + r8 + ((sel >> 1) << 3);
                uint32_t bb[4];
                LDSM4(bb[0], bb[1], bb[2], bb[3],
                      sK + (uint32_t)rowB * 512u + (uint32_t)((((ks << 1) + dselB) ^ (rowB & 7)) << 4));
                MMAH16816(sacc[nf2 * 2 + 0], a, bb[0], bb[1]);
                MMAH16816(sacc[nf2 * 2 + 1], a, bb[2], bb[3]);
            }
        }

        float mx1 = -INFINITY, mx2 = -INFINITY;
#pragma unroll
        for (int nf = 0; nf < 8; nf++)
#pragma unroll
            for (int e = 0; e < 4; e++) {
                float s = sacc[nf][e];
                float cpv = 50.f - __fdividef(100.f, __expf(0.04f * s) + 1.f);
                if (diag) {
                    int col = s0 + nf * 8 + ((lane & 3) << 1) + (e & 1);
                    int row = qbase + ((e < 2) ? r1g : r2g);
                    if (col > row) cpv = -INFINITY;
                }
                sacc[nf][e] = cpv;
                if (e < 2) mx1 = fmaxf(mx1, cpv); else mx2 = fmaxf(mx2, cpv);
            }
        mx1 = fmaxf(mx1, __shfl_xor_sync(0xffffffffu, mx1, 1));
        mx1 = fmaxf(mx1, __shfl_xor_sync(0xffffffffu, mx1, 2));
        mx2 = fmaxf(mx2, __shfl_xor_sync(0xffffffffu, mx2, 1));
        mx2 = fmaxf(mx2, __shfl_xor_sync(0xffffffffu, mx2, 2));
        float mn1 = fmaxf(m1, mx1), mn2 = fmaxf(m2, mx2);
        float corr1 = __expf(m1 - mn1), corr2 = __expf(m2 - mn2);
        m1 = mn1; m2 = mn2;

        uint32_t pfrag[4][4];
        float sum1 = 0.f, sum2 = 0.f;
#pragma unroll
        for (int nf = 0; nf < 8; nf++) {
            float p0 = __expf(sacc[nf][0] - mn1);
            float p1 = __expf(sacc[nf][1] - mn1);
            float p2 = __expf(sacc[nf][2] - mn2);
            float p3 = __expf(sacc[nf][3] - mn2);
            sum1 += p0 + p1; sum2 += p2 + p3;
            int ks = nf >> 1, hi = nf & 1;
            pfrag[ks][hi * 2 + 0] = packh2(p0, p1);
            pfrag[ks][hi * 2 + 1] = packh2(p2, p3);
        }
        sum1 += __shfl_xor_sync(0xffffffffu, sum1, 1);
        sum1 += __shfl_xor_sync(0xffffffffu, sum1, 2);
        sum2 += __shfl_xor_sync(0xffffffffu, sum2, 1);
        sum2 += __shfl_xor_sync(0xffffffffu, sum2, 2);
        l1 = l1 * corr1 + sum1;
        l2 = l2 * corr2 + sum2;

#pragma unroll
        for (int nf = 0; nf < 32; nf++) {
            oacc[nf][0] *= corr1; oacc[nf][1] *= corr1;
            oacc[nf][2] *= corr2; oacc[nf][3] *= corr2;
        }

#pragma unroll
        for (int ks = 0; ks < 4; ks++) {
            int rowV = ks * 16 + r8 + ((sel & 1) << 3);
            uint32_t vBase = sV + (uint32_t)rowV * 512u;
            int rVx = rowV & 7;
#pragma unroll
            for (int nf2 = 0; nf2 < 16; nf2++) {
                int chunk = nf2 * 2 + (sel >> 1);
                uint32_t bb[4];
                LDSM4T(bb[0], bb[1], bb[2], bb[3], vBase + (uint32_t)((chunk ^ rVx) << 4));
                MMAH16816(oacc[nf2 * 2 + 0], pfrag[ks], bb[0], bb[1]);
                MMAH16816(oacc[nf2 * 2 + 1], pfrag[ks], bb[2], bb[3]);
            }
        }
        __syncthreads();
    }

    float inv1 = 1.f / l1;
    float inv2 = 1.f / l2;
    int t1 = qbase + r1g, t2 = qbase + r2g;
    __half* o1 = Oh + ((size_t)(b * T_LEN + t1)) * (N_HEADS * H_DIM) + n * H_DIM + ((lane & 3) << 1);
    __half* o2 = Oh + ((size_t)(b * T_LEN + t2)) * (N_HEADS * H_DIM) + n * H_DIM + ((lane & 3) << 1);
#pragma unroll
    for (int nf = 0; nf < 32; nf++) {
        __half2 v1 = __floats2half2_rn(oacc[nf][0] * inv1, oacc[nf][1] * inv1);
        __half2 v2 = __floats2half2_rn(oacc[nf][2] * inv2, oacc[nf][3] * inv2);
        *(__half2*)(o1 + nf * 8) = v1;
        *(__half2*)(o2 + nf * 8) = v2;
    }
}

// ---------------- launch ----------------
extern "C" void kernel_launch(void* const* d_in, const int* in_sizes, int n_in,
                              void* d_out, int out_size)
{
    (void)in_sizes; (void)n_in; (void)out_size;
    const float* hs  = (const float*)d_in[0];
    const float* enc = (const float*)d_in[1];
    const float* qw  = (const float*)d_in[4];
    const float* kw  = (const float*)d_in[5];
    const float* vw  = (const float*)d_in[6];
    const float* ow  = (const float*)d_in[7];
    const float* qsc = (const float*)d_in[8];
    const float* ksc = (const float*)d_in[9];
    float* out = (float*)d_out;

    __half *kraw, *q16, *k16, *v16;
    cudaGetSymbolAddress((void**)&kraw, g_kraw);
    cudaGetSymbolAddress((void**)&q16, g_q16);
    cudaGetSymbolAddress((void**)&k16, g_k16);
    cudaGetSymbolAddress((void**)&v16, g_v16);
    __half *hs2, *enc2, *qw2, *kw2, *vw2, *ow2, *at2;
    cudaGetSymbolAddress((void**)&hs2, g_hs2);
    cudaGetSymbolAddress((void**)&enc2, g_enc2);
    cudaGetSymbolAddress((void**)&qw2, g_qw2);
    cudaGetSymbolAddress((void**)&kw2, g_kw2);
    cudaGetSymbolAddress((void**)&vw2, g_vw2);
    cudaGetSymbolAddress((void**)&ow2, g_ow2);
    cudaGetSymbolAddress((void**)&at2, g_at2);

    static int cfg = 0;
    static cudaStream_t s1, s2;
    static cudaEvent_t eFork, eHs, eEnc, eQw, eKw, eKdone, eVdone, eOw, eF1, eOg1;
    if (!cfg) {
        cudaFuncSetAttribute(gemm_hmma, cudaFuncAttributeMaxDynamicSharedMemorySize, GEMM_SMEM);
        cudaFuncSetAttribute(flash2_hmma, cudaFuncAttributeMaxDynamicSharedMemorySize, FH2_SMEM);
        cudaStreamCreateWithFlags(&s1, cudaStreamNonBlocking);
        cudaStreamCreateWithFlags(&s2, cudaStreamNonBlocking);
        cudaEventCreateWithFlags(&eFork, cudaEventDisableTiming);
        cudaEventCreateWithFlags(&eHs, cudaEventDisableTiming);
        cudaEventCreateWithFlags(&eEnc, cudaEventDisableTiming);
        cudaEventCreateWithFlags(&eQw, cudaEventDisableTiming);
        cudaEventCreateWithFlags(&eKw, cudaEventDisableTiming);
        cudaEventCreateWithFlags(&eKdone, cudaEventDisableTiming);
        cudaEventCreateWithFlags(&eVdone, cudaEventDisableTiming);
        cudaEventCreateWithFlags(&eOw, cudaEventDisableTiming);
        cudaEventCreateWithFlags(&eF1, cudaEventDisableTiming);
        cudaEventCreateWithFlags(&eOg1, cudaEventDisableTiming);
        cfg = 1;
    }

    const long long kvBS = (long long)S_LEN * K_HEADS * H_DIM;
    const long long pHS = (long long)D_DIM * H_DIM;

    // FORK
    cudaEventRecord(eFork, 0);
    cudaStreamWaitEvent(s1, eFork, 0);
    cudaStreamWaitEvent(s2, eFork, 0);

    // s0: hs convert
    a2h_kernel<<<(4096LL * 2048) / 1024, 256, 0, 0>>>(hs, hs2);
    cudaEventRecord(eHs, 0);
    // s1: enc convert
    a2h_kernel<<<(4096LL * 2048) / 1024, 256, 0, s1>>>(enc, enc2);
    cudaEventRecord(eEnc, s1);
    // s2: weight converts
    wsplit_kernel<<<dim3(4096 / 32, D_DIM / 32), 256, 0, s2>>>(qw, qw2, D_DIM, H_DIM, pHS, H_DIM);
    cudaEventRecord(eQw, s2);
    wsplit_kernel<<<dim3(2048 / 32, D_DIM / 32), 256, 0, s2>>>(kw, kw2, D_DIM, H_DIM, pHS, H_DIM);
    cudaEventRecord(eKw, s2);
    wsplit_kernel<<<dim3(2048 / 32, D_DIM / 32), 256, 0, s2>>>(vw, vw2, D_DIM, H_DIM, pHS, H_DIM);

    // s0: Q path (GEMM -> fp16 at2, rms fp16->fp16)
    cudaStreamWaitEvent(0, eQw, 0);
    gemm_hmma<<<dim3(32, 32), 128, GEMM_SMEM, 0>>>(hs2, qw2, at2, 2048, 4096, 0LL, 0, 4096, 1, 32, 0, 0);
    rms_rope_w_kernel<<<B_SZ * T_LEN * N_HEADS / 8, 256, 0, 0>>>(at2, q16, qsc, N_HEADS, T_LEN, T_LEN, 0, 1, 0.0625f);

    // s1: K path (GEMMs -> fp16 kraw)
    cudaStreamWaitEvent(s1, eHs, 0);
    cudaStreamWaitEvent(s1, eKw, 0);
    gemm_hmma<<<dim3(16, 32), 128, GEMM_SMEM, s1>>>(hs2, kw2, kraw, 2048, T_LEN, kvBS, 0, 2048, 1, 32, 0, 0);
    gemm_hmma<<<dim3(16, 32), 128, GEMM_SMEM, s1>>>(enc2, kw2, kraw, 2048, E_LEN, kvBS, T_LEN, 2048, 1, 32, 0, 0);
    rms_rope_w_kernel<<<B_SZ * T_LEN * K_HEADS / 8, 256, 0, s1>>>(kraw, k16, ksc, K_HEADS, T_LEN, S_LEN, 0, 1, 1.0f);
    rms_rope_w_kernel<<<B_SZ * E_LEN * K_HEADS / 8, 256, 0, s1>>>(kraw, k16, ksc, K_HEADS, E_LEN, S_LEN, T_LEN, 0, 1.0f);
    cudaEventRecord(eKdone, s1);

    // s2: V path
    cudaStreamWaitEvent(s2, eHs, 0);
    cudaStreamWaitEvent(s2, eEnc, 0);
    gemm_hmma<<<dim3(16, 32), 128, GEMM_SMEM, s2>>>(hs2, vw2, v16, 2048, T_LEN, kvBS, 0, 2048, 1, 32, 0, 0);
    gemm_hmma<<<dim3(16, 32), 128, GEMM_SMEM, s2>>>(enc2, vw2, v16, 2048, E_LEN, kvBS, T_LEN, 2048, 1, 32, 0, 0);
    cudaEventRecord(eVdone, s2);
    wsplit_kernel<<<dim3(2048 / 32, 4096 / 32), 256, 0, s2>>>(ow, ow2, 4096, D_DIM, 0LL, D_DIM);
    cudaEventRecord(eOw, s2);

    // s0: flash half 1 (qt 0..3)
    cudaStreamWaitEvent(0, eKdone, 0);
    cudaStreamWaitEvent(0, eVdone, 0);
    flash2_hmma<<<dim3(4, N_HEADS, B_SZ), 256, FH2_SMEM, 0>>>(q16, k16, v16, at2, 0);
    cudaEventRecord(eF1, 0);
    // s0: flash half 2 (qt 4..7)
    flash2_hmma<<<dim3(4, N_HEADS, B_SZ), 256, FH2_SMEM, 0>>>(q16, k16, v16, at2, 4);

    // s1: O-GEMM half 1 (rows t<512) overlaps flash half 2
    cudaStreamWaitEvent(s1, eF1, 0);
    cudaStreamWaitEvent(s1, eOw, 0);
    gemm_hmma<<<dim3(16, 16), 128, GEMM_SMEM, s1>>>(at2, ow2, out, 4096, 4096, 0LL, 0, 2048, 0, 4, 1024, 0);
    cudaEventRecord(eOg1, s1);

    // s0: O-GEMM half 2 (rows t>=512), join all
    cudaStreamWaitEvent(0, eOw, 0);
    cudaStreamWaitEvent(0, eOg1, 0);
    gemm_hmma<<<dim3(16, 16), 128, GEMM_SMEM, 0>>>(at2, ow2, out, 4096, 4096, 0LL, 0, 2048, 0, 4, 1024, 512);
}

// round 16
// speedup vs baseline: 1.0185x; 1.0185x over previous
#include <cuda_runtime.h>
#include <cuda_fp16.h>
#include <stdint.h>
#include <math.h>

#define B_SZ 4
#define T_LEN 1024
#define E_LEN 1024
#define S_LEN 2048
#define D_DIM 2048
#define H_DIM 256
#define N_HEADS 16
#define K_HEADS 8

__device__ float g_q[(size_t)B_SZ * T_LEN * N_HEADS * H_DIM];
__device__ float g_k[(size_t)B_SZ * S_LEN * K_HEADS * H_DIM];
__device__ __half g_q16[(size_t)B_SZ * T_LEN * N_HEADS * H_DIM];
__device__ __half g_k16[(size_t)B_SZ * S_LEN * K_HEADS * H_DIM];
__device__ __half g_v16[(size_t)B_SZ * S_LEN * K_HEADS * H_DIM];
__device__ __half g_hs2 [(size_t)4096 * 2048];
__device__ __half g_enc2[(size_t)4096 * 2048];
__device__ __half g_qw2 [(size_t)4096 * 2048];
__device__ __half g_kw2 [(size_t)2048 * 2048];
__device__ __half g_vw2 [(size_t)2048 * 2048];
__device__ __half g_ow2 [(size_t)2048 * 4096];
__device__ __half g_at2 [(size_t)4096 * 4096];

// ---------------- helpers ----------------
__device__ __forceinline__ uint32_t smem_u32(const void* p) {
    uint32_t a;
    asm("{ .reg .u64 t; cvta.to.shared.u64 t, %1; cvt.u32.u64 %0, t; }" : "=r"(a) : "l"(p));
    return a;
}
#define CP16(dst, src) \
    asm volatile("cp.async.cg.shared.global [%0], [%1], 16;" :: "r"(dst), "l"(src) : "memory")
#define CP_COMMIT asm volatile("cp.async.commit_group;" ::: "memory")
#define CP_WAIT2  asm volatile("cp.async.wait_group 2;" ::: "memory")
#define CP_WAIT1  asm volatile("cp.async.wait_group 1;" ::: "memory")
#define CP_WAIT0  asm volatile("cp.async.wait_group 0;" ::: "memory")
#define LDSM4(r0, r1, r2, r3, addr) \
    asm volatile("ldmatrix.sync.aligned.m8n8.x4.shared.b16 {%0,%1,%2,%3}, [%4];" \
        : "=r"(r0), "=r"(r1), "=r"(r2), "=r"(r3) : "r"(addr))
#define LDSM4T(r0, r1, r2, r3, addr) \
    asm volatile("ldmatrix.sync.aligned.m8n8.x4.trans.shared.b16 {%0,%1,%2,%3}, [%4];" \
        : "=r"(r0), "=r"(r1), "=r"(r2), "=r"(r3) : "r"(addr))
#define MMAH16816(d, a, b0, b1) \
    asm volatile("mma.sync.aligned.m16n8k16.row.col.f32.f16.f16.f32 " \
        "{%0,%1,%2,%3}, {%4,%5,%6,%7}, {%8,%9}, {%0,%1,%2,%3};" \
        : "+f"((d)[0]), "+f"((d)[1]), "+f"((d)[2]), "+f"((d)[3]) \
        : "r"((a)[0]), "r"((a)[1]), "r"((a)[2]), "r"((a)[3]), "r"(b0), "r"(b1))

__device__ __forceinline__ uint32_t gsw(int row, int kchunk) {
    return (uint32_t)(row * 128 + ((kchunk ^ (row & 7)) << 4));
}
__device__ __forceinline__ uint32_t fsw(int row, int kbyte) {
    return (uint32_t)(row * 512 + ((((kbyte >> 4) ^ (row & 7))) << 4) + (kbyte & 15));
}
__device__ __forceinline__ uint32_t packh2(float a, float b) {
    __half2 h = __floats2half2_rn(a, b);
    return *(uint32_t*)&h;
}

// ---------------- convert kernels ----------------
__global__ __launch_bounds__(256) void a2h_kernel(
    const float* __restrict__ X, __half* __restrict__ Y)
{
    size_t idx = ((size_t)blockIdx.x * 256 + threadIdx.x) * 4;
    float4 v = *(const float4*)(X + idx);
    __half2 h0 = __floats2half2_rn(v.x, v.y);
    __half2 h1 = __floats2half2_rn(v.z, v.w);
    *(uint2*)(Y + idx) = make_uint2(*(uint32_t*)&h0, *(uint32_t*)&h1);
}

__global__ __launch_bounds__(256) void wsplit_kernel(
    const float* __restrict__ W, __half* __restrict__ Yt,
    int Kd, int cph, long long hstr, int krs)
{
    __shared__ float t[32][33];
    int k0 = blockIdx.y * 32, j0 = blockIdx.x * 32;
    int tx = threadIdx.x & 31, ty8 = threadIdx.x >> 5;
#pragma unroll
    for (int i = 0; i < 4; i++) {
        int kl = ty8 + i * 8;
        int j = j0 + tx;
        t[kl][tx] = W[(size_t)(j / cph) * hstr + (size_t)(k0 + kl) * krs + (j % cph)];
    }
    __syncthreads();
#pragma unroll
    for (int i = 0; i < 4; i++) {
        int j = j0 + ty8 + i * 8;
        int k = k0 + tx;
        Yt[(size_t)j * Kd + k] = __float2half(t[tx][ty8 + i * 8]);
    }
}

// ---------------- HMMA fp16 GEMM (R14, unchanged) ----------------
#define GSTAGES 3
#define STG_BYTES 32768
#define GEMM_SMEM (GSTAGES * STG_BYTES)

__global__ void __launch_bounds__(128, 2) gemm_hmma(
    const __half* __restrict__ A, const __half* __restrict__ Bw,
    void* __restrict__ Cv, int Kp, int Mpb, long long outBS, int rowOff, int ldc,
    int outHalf, int mGT, int mGS, int mOff)
{
    extern __shared__ char smraw[];
    const uint32_t sb = smem_u32(smraw);
    const int tid = threadIdx.x;
    const int lane = tid & 31, wid = tid >> 5;
    const int wm = wid & 1, wn = wid >> 1;
    const int m0 = (blockIdx.y / mGT) * mGS + (blockIdx.y % mGT) * 128 + mOff;
    const int n0 = blockIdx.x * 128;
    const int nIter = Kp >> 6;

    const int crow = tid >> 3;
    const int ckc = tid & 7;
    const uint32_t csw = gsw(crow, ckc);
    const __half* ga = A + (size_t)(m0 + crow) * Kp + ckc * 8;
    const __half* gb = Bw + (size_t)(n0 + crow) * Kp + ckc * 8;

    const int r8 = lane & 7, sel = lane >> 3;
    uint32_t aRB[4]; int aRX[4];
    const int dselA = sel >> 1;
#pragma unroll
    for (int mf = 0; mf < 4; mf++) {
        int row = wm * 64 + mf * 16 + r8 + ((sel & 1) << 3);
        aRB[mf] = (uint32_t)(row * 128);
        aRX[mf] = row & 7;
    }
    uint32_t bRB[4]; int bRX[4];
    const int dselB = sel & 1;
#pragma unroll
    for (int np = 0; np < 4; np++) {
        int row = wn * 64 + np * 16 + r8 + ((sel >> 1) << 3);
        bRB[np] = 16384u + (uint32_t)(row * 128);
        bRX[np] = row & 7;
    }

    float acc[4][8][4];
#pragma unroll
    for (int mf = 0; mf < 4; mf++)
#pragma unroll
        for (int nf = 0; nf < 8; nf++)
#pragma unroll
            for (int q = 0; q < 4; q++) acc[mf][nf][q] = 0.f;

#pragma unroll
    for (int s = 0; s < 2; s++) {
        uint32_t base = sb + (uint32_t)s * STG_BYTES;
        const __half* pa = ga + s * 64;
        const __half* pb = gb + s * 64;
#pragma unroll
        for (int p = 0; p < 8; p++) {
            uint32_t so = csw + (uint32_t)p * 2048u;
            CP16(base + so, pa + (size_t)p * 16 * Kp);
            CP16(base + 16384u + so, pb + (size_t)p * 16 * Kp);
        }
        CP_COMMIT;
    }

    for (int it = 0; it < nIter; it++) {
        if (it + 2 < nIter) {
            int s = (it + 2) % GSTAGES;
            uint32_t base = sb + (uint32_t)s * STG_BYTES;
            const __half* pa = ga + (size_t)(it + 2) * 64;
            const __half* pb = gb + (size_t)(it + 2) * 64;
#pragma unroll
            for (int p = 0; p < 8; p++) {
                uint32_t so = csw + (uint32_t)p * 2048u;
                CP16(base + so, pa + (size_t)p * 16 * Kp);
                CP16(base + 16384u + so, pb + (size_t)p * 16 * Kp);
            }
        }
        CP_COMMIT;
        CP_WAIT2;
        __syncthreads();

        uint32_t sbase = sb + (uint32_t)(it % GSTAGES) * STG_BYTES;
#pragma unroll
        for (int ks = 0; ks < 4; ks++) {
            uint32_t af[4][4];
#pragma unroll
            for (int mf = 0; mf < 4; mf++)
                LDSM4(af[mf][0], af[mf][1], af[mf][2], af[mf][3],
                      sbase + aRB[mf] + (uint32_t)((((ks << 1) + dselA) ^ aRX[mf]) << 4));
            uint32_t bf[4][4];
#pragma unroll
            for (int np = 0; np < 4; np++)
                LDSM4(bf[np][0], bf[np][1], bf[np][2], bf[np][3],
                      sbase + bRB[np] + (uint32_t)((((ks << 1) + dselB) ^ bRX[np]) << 4));
#pragma unroll
            for (int mf = 0; mf < 4; mf++)
#pragma unroll
                for (int np = 0; np < 4; np++) {
                    MMAH16816(acc[mf][np * 2 + 0], af[mf], bf[np][0], bf[np][1]);
                    MMAH16816(acc[mf][np * 2 + 1], af[mf], bf[np][2], bf[np][3]);
                }
        }
        __syncthreads();
    }

#pragma unroll
    for (int mf = 0; mf < 4; mf++)
#pragma unroll
        for (int rh = 0; rh < 2; rh++) {
            int gr = m0 + wm * 64 + mf * 16 + (lane >> 2) + rh * 8;
            int bi = gr / Mpb;
            int rr = gr - bi * Mpb;
            size_t base = (size_t)bi * outBS + (size_t)(rr + rowOff) * ldc
                        + n0 + wn * 64 + (lane & 3) * 2;
            if (outHalf) {
                __half* rowp = (__half*)Cv + base;
#pragma unroll
                for (int nf = 0; nf < 8; nf++) {
                    __half2 v = __floats2half2_rn(acc[mf][nf][rh * 2 + 0], acc[mf][nf][rh * 2 + 1]);
                    *(__half2*)(rowp + nf * 8) = v;
                }
            } else {
                float* rowp = (float*)Cv + base;
#pragma unroll
                for (int nf = 0; nf < 8; nf++) {
                    float2 v = make_float2(acc[mf][nf][rh * 2 + 0], acc[mf][nf][rh * 2 + 1]);
                    *(float2*)(rowp + nf * 8) = v;
                }
            }
        }
}

// ---------------- RMS-norm (+RoPE) fp32 -> fp16, warp-per-row ----------------
// RoPE position = rowStart + t (identical to previous behavior for all doRope
// calls, which had rowStart == 0; enables M-split Q halves).
__global__ __launch_bounds__(256) void rms_rope_w_kernel(
    const float* __restrict__ buf, __half* __restrict__ outh,
    const float* __restrict__ scale,
    int heads, int rowsPerBatch, int bufRPB, int rowStart, int doRope, float outScale)
{
    int rowIdx = blockIdx.x * 8 + (threadIdx.x >> 5);
    int lane = threadIdx.x & 31;
    int head = rowIdx % heads;
    int tmp = rowIdx / heads;
    int t = tmp % rowsPerBatch;
    int b = tmp / rowsPerBatch;
    size_t off = ((size_t)((size_t)b * bufRPB + rowStart + t) * heads + head) * H_DIM;

    float4 x1 = *(const float4*)(buf + off + lane * 4);
    float4 x2 = *(const float4*)(buf + off + 128 + lane * 4);
    float ss = x1.x * x1.x + x1.y * x1.y + x1.z * x1.z + x1.w * x1.w
             + x2.x * x2.x + x2.y * x2.y + x2.z * x2.z + x2.w * x2.w;
#pragma unroll
    for (int o = 16; o > 0; o >>= 1) ss += __shfl_xor_sync(0xffffffffu, ss, o);
    float rinv = rsqrtf(ss * (1.f / 256.f) + 1e-6f) * outScale;

    float4 s1 = *(const float4*)(scale + lane * 4);
    float4 s2 = *(const float4*)(scale + 128 + lane * 4);
    float y1[4] = { x1.x * rinv * (1.f + s1.x), x1.y * rinv * (1.f + s1.y),
                    x1.z * rinv * (1.f + s1.z), x1.w * rinv * (1.f + s1.w) };
    float y2[4] = { x2.x * rinv * (1.f + s2.x), x2.y * rinv * (1.f + s2.y),
                    x2.z * rinv * (1.f + s2.z), x2.w * rinv * (1.f + s2.w) };
    float o1[4], o2[4];
    if (doRope) {
        float pos = (float)(rowStart + t);
#pragma unroll
        for (int i = 0; i < 4; i++) {
            float ang = pos * exp2f(-(float)(lane * 4 + i) * 0.10381025296522988f);
            float sn, cs;
            sincosf(ang, &sn, &cs);
            o1[i] = y1[i] * cs - y2[i] * sn;
            o2[i] = y2[i] * cs + y1[i] * sn;
        }
    } else {
#pragma unroll
        for (int i = 0; i < 4; i++) { o1[i] = y1[i]; o2[i] = y2[i]; }
    }
    __half2 a0 = __floats2half2_rn(o1[0], o1[1]);
    __half2 a1 = __floats2half2_rn(o1[2], o1[3]);
    __half2 b0 = __floats2half2_rn(o2[0], o2[1]);
    __half2 b1 = __floats2half2_rn(o2[2], o2[3]);
    *(uint2*)(outh + off + lane * 4) = make_uint2(*(uint32_t*)&a0, *(uint32_t*)&a1);
    *(uint2*)(outh + off + 128 + lane * 4) = make_uint2(*(uint32_t*)&b0, *(uint32_t*)&b1);
}

// ---------------- flash v3 (unchanged R14) ----------------
#define F2_KB 65536u
#define F2_VB 131072u
#define F2_ST 32768u
#define FH2_SMEM 196608

__global__ void __launch_bounds__(256, 1) flash2_hmma(
    const __half* __restrict__ Qh, const __half* __restrict__ Kh,
    const __half* __restrict__ Vh, __half* __restrict__ Oh, int qt0)
{
    extern __shared__ char smraw[];
    const uint32_t sb = smem_u32(smraw);
    const int tid = threadIdx.x, lane = tid & 31, w = tid >> 5;
    const int qt = blockIdx.x + qt0, n = blockIdx.y, b = blockIdx.z;
    const int kh = n >> 1, qbase = qt << 7;

    const char* qg = (const char*)(Qh + ((size_t)(b * T_LEN + qbase) * N_HEADS + n) * H_DIM);
#pragma unroll
    for (int p = 0; p < 16; p++) {
        int idx = tid + p * 256;
        int r = idx >> 5, c = idx & 31;
        CP16(sb + fsw(r, c * 16), qg + (size_t)r * (N_HEADS * H_DIM * 2) + c * 16);
    }
    CP_COMMIT;

    const char* kg = (const char*)(Kh + ((size_t)b * S_LEN * K_HEADS + kh) * H_DIM);
    const char* vg = (const char*)(Vh + ((size_t)b * S_LEN * K_HEADS + kh) * H_DIM);
    const int kvstride = K_HEADS * H_DIM * 2;

    const int nSelf = (qt + 1) << 1;
    const int nT = nSelf + (E_LEN >> 6);

#pragma unroll
    for (int p = 0; p < 8; p++) {
        int idx = tid + p * 256;
        int r = idx >> 5, c = idx & 31;
        uint32_t sw = fsw(r, c * 16);
        CP16(sb + F2_KB + sw, kg + (size_t)r * kvstride + c * 16);
        CP16(sb + F2_VB + sw, vg + (size_t)r * kvstride + c * 16);
    }
    CP_COMMIT;

    float oacc[32][4];
#pragma unroll
    for (int nf = 0; nf < 32; nf++)
#pragma unroll
        for (int q = 0; q < 4; q++) oacc[nf][q] = 0.f;
    float m1 = -INFINITY, m2 = -INFINITY, l1 = 0.f, l2 = 0.f;

    const int r8 = lane & 7, sel = lane >> 3;
    const int rowA = w * 16 + r8 + ((sel & 1) << 3);
    const int dselA = sel >> 1;
    const int dselB = sel & 1;
    const int r1g = w * 16 + (lane >> 2), r2g = r1g + 8;
    const uint32_t aBaseQ = sb + (uint32_t)rowA * 512u;
    const int rowAx = rowA & 7;

    for (int t = 0; t < nT; t++) {
        if (t + 1 < nT) {
            int s0n = (t + 1 < nSelf) ? ((t + 1) << 6) : (T_LEN + ((t + 1 - nSelf) << 6));
            uint32_t kb = sb + F2_KB + (uint32_t)((t + 1) & 1) * F2_ST;
            uint32_t vb = sb + F2_VB + (uint32_t)((t + 1) & 1) * F2_ST;
#pragma unroll
            for (int p = 0; p < 8; p++) {
                int idx = tid + p * 256;
                int r = idx >> 5, c = idx & 31;
                uint32_t sw = fsw(r, c * 16);
                CP16(kb + sw, kg + (size_t)(s0n + r) * kvstride + c * 16);
                CP16(vb + sw, vg + (size_t)(s0n + r) * kvstride + c * 16);
            }
            CP_COMMIT;
            CP_WAIT1;
        } else {
            CP_WAIT0;
        }
        __syncthreads();

        const int s0 = (t < nSelf) ? (t << 6) : (T_LEN + ((t - nSelf) << 6));
        const bool diag = (t >= nSelf - 2) && (t < nSelf);
        const uint32_t sK = sb + F2_KB + (uint32_t)(t & 1) * F2_ST;
        const uint32_t sV = sb + F2_VB + (uint32_t)(t & 1) * F2_ST;

        float sacc[8][4];
#pragma unroll
        for (int nf = 0; nf < 8; nf++)
#pragma unroll
            for (int q = 0; q < 4; q++) sacc[nf][q] = 0.f;
#pragma unroll 4
        for (int ks = 0; ks < 16; ks++) {
            uint32_t a[4];
            LDSM4(a[0], a[1], a[2], a[3], aBaseQ + (uint32_t)((((ks << 1) + dselA) ^ rowAx) << 4));
#pragma unroll
            for (int nf2 = 0; nf2 < 4; nf2++) {
                int rowB = nf2 * 16 + r8 + ((sel >> 1) << 3);
                uint32_t bb[4];
                LDSM4(bb[0], bb[1], bb[2], bb[3],
                      sK + (uint32_t)rowB * 512u + (uint32_t)((((ks << 1) + dselB) ^ (rowB & 7)) << 4));
                MMAH16816(sacc[nf2 * 2 + 0], a, bb[0], bb[1]);
                MMAH16816(sacc[nf2 * 2 + 1], a, bb[2], bb[3]);
            }
        }

        float mx1 = -INFINITY, mx2 = -INFINITY;
#pragma unroll
        for (int nf = 0; nf < 8; nf++)
#pragma unroll
            for (int e = 0; e < 4; e++) {
                float s = sacc[nf][e];
                float cpv = 50.f - __fdividef(100.f, __expf(0.04f * s) + 1.f);
                if (diag) {
                    int col = s0 + nf * 8 + ((lane & 3) << 1) + (e & 1);
                    int row = qbase + ((e < 2) ? r1g : r2g);
                    if (col > row) cpv = -INFINITY;
                }
                sacc[nf][e] = cpv;
                if (e < 2) mx1 = fmaxf(mx1, cpv); else mx2 = fmaxf(mx2, cpv);
            }
        mx1 = fmaxf(mx1, __shfl_xor_sync(0xffffffffu, mx1, 1));
        mx1 = fmaxf(mx1, __shfl_xor_sync(0xffffffffu, mx1, 2));
        mx2 = fmaxf(mx2, __shfl_xor_sync(0xffffffffu, mx2, 1));
        mx2 = fmaxf(mx2, __shfl_xor_sync(0xffffffffu, mx2, 2));
        float mn1 = fmaxf(m1, mx1), mn2 = fmaxf(m2, mx2);
        float corr1 = __expf(m1 - mn1), corr2 = __expf(m2 - mn2);
        m1 = mn1; m2 = mn2;

        uint32_t pfrag[4][4];
        float sum1 = 0.f, sum2 = 0.f;
#pragma unroll
        for (int nf = 0; nf < 8; nf++) {
            float p0 = __expf(sacc[nf][0] - mn1);
            float p1 = __expf(sacc[nf][1] - mn1);
            float p2 = __expf(sacc[nf][2] - mn2);
            float p3 = __expf(sacc[nf][3] - mn2);
            sum1 += p0 + p1; sum2 += p2 + p3;
            int ks = nf >> 1, hi = nf & 1;
            pfrag[ks][hi * 2 + 0] = packh2(p0, p1);
            pfrag[ks][hi * 2 + 1] = packh2(p2, p3);
        }
        sum1 += __shfl_xor_sync(0xffffffffu, sum1, 1);
        sum1 += __shfl_xor_sync(0xffffffffu, sum1, 2);
        sum2 += __shfl_xor_sync(0xffffffffu, sum2, 1);
        sum2 += __shfl_xor_sync(0xffffffffu, sum2, 2);
        l1 = l1 * corr1 + sum1;
        l2 = l2 * corr2 + sum2;

#pragma unroll
        for (int nf = 0; nf < 32; nf++) {
            oacc[nf][0] *= corr1; oacc[nf][1] *= corr1;
            oacc[nf][2] *= corr2; oacc[nf][3] *= corr2;
        }

#pragma unroll
        for (int ks = 0; ks < 4; ks++) {
            int rowV = ks * 16 + r8 + ((sel & 1) << 3);
            uint32_t vBase = sV + (uint32_t)rowV * 512u;
            int rVx = rowV & 7;
#pragma unroll
            for (int nf2 = 0; nf2 < 16; nf2++) {
                int chunk = nf2 * 2 + (sel >> 1);
                uint32_t bb[4];
                LDSM4T(bb[0], bb[1], bb[2], bb[3], vBase + (uint32_t)((chunk ^ rVx) << 4));
                MMAH16816(oacc[nf2 * 2 + 0], pfrag[ks], bb[0], bb[1]);
                MMAH16816(oacc[nf2 * 2 + 1], pfrag[ks], bb[2], bb[3]);
            }
        }
        __syncthreads();
    }

    float inv1 = 1.f / l1;
    float inv2 = 1.f / l2;
    int t1 = qbase + r1g, t2 = qbase + r2g;
    __half* o1 = Oh + ((size_t)(b * T_LEN + t1)) * (N_HEADS * H_DIM) + n * H_DIM + ((lane & 3) << 1);
    __half* o2 = Oh + ((size_t)(b * T_LEN + t2)) * (N_HEADS * H_DIM) + n * H_DIM + ((lane & 3) << 1);
#pragma unroll
    for (int nf = 0; nf < 32; nf++) {
        __half2 v1 = __floats2half2_rn(oacc[nf][0] * inv1, oacc[nf][1] * inv1);
        __half2 v2 = __floats2half2_rn(oacc[nf][2] * inv2, oacc[nf][3] * inv2);
        *(__half2*)(o1 + nf * 8) = v1;
        *(__half2*)(o2 + nf * 8) = v2;
    }
}

// ---------------- launch: DAG + Q-split + flash/O-GEMM pipeline ----------------
extern "C" void kernel_launch(void* const* d_in, const int* in_sizes, int n_in,
                              void* d_out, int out_size)
{
    (void)in_sizes; (void)n_in; (void)out_size;
    const float* hs  = (const float*)d_in[0];
    const float* enc = (const float*)d_in[1];
    const float* qw  = (const float*)d_in[4];
    const float* kw  = (const float*)d_in[5];
    const float* vw  = (const float*)d_in[6];
    const float* ow  = (const float*)d_in[7];
    const float* qsc = (const float*)d_in[8];
    const float* ksc = (const float*)d_in[9];
    float* out = (float*)d_out;

    float *qb, *kb;
    cudaGetSymbolAddress((void**)&qb, g_q);
    cudaGetSymbolAddress((void**)&kb, g_k);
    __half *q16, *k16, *v16;
    cudaGetSymbolAddress((void**)&q16, g_q16);
    cudaGetSymbolAddress((void**)&k16, g_k16);
    cudaGetSymbolAddress((void**)&v16, g_v16);
    __half *hs2, *enc2, *qw2, *kw2, *vw2, *ow2, *at2;
    cudaGetSymbolAddress((void**)&hs2, g_hs2);
    cudaGetSymbolAddress((void**)&enc2, g_enc2);
    cudaGetSymbolAddress((void**)&qw2, g_qw2);
    cudaGetSymbolAddress((void**)&kw2, g_kw2);
    cudaGetSymbolAddress((void**)&vw2, g_vw2);
    cudaGetSymbolAddress((void**)&ow2, g_ow2);
    cudaGetSymbolAddress((void**)&at2, g_at2);

    static int cfg = 0;
    static cudaStream_t s1, s2;
    static cudaEvent_t eFork, eHs, eEnc, eQw, eKw, eKdone, eVdone, eOw, eQ2, eF1, eOg1;
    if (!cfg) {
        cudaFuncSetAttribute(gemm_hmma, cudaFuncAttributeMaxDynamicSharedMemorySize, GEMM_SMEM);
        cudaFuncSetAttribute(flash2_hmma, cudaFuncAttributeMaxDynamicSharedMemorySize, FH2_SMEM);
        cudaStreamCreateWithFlags(&s1, cudaStreamNonBlocking);
        cudaStreamCreateWithFlags(&s2, cudaStreamNonBlocking);
        cudaEventCreateWithFlags(&eFork, cudaEventDisableTiming);
        cudaEventCreateWithFlags(&eHs, cudaEventDisableTiming);
        cudaEventCreateWithFlags(&eEnc, cudaEventDisableTiming);
        cudaEventCreateWithFlags(&eQw, cudaEventDisableTiming);
        cudaEventCreateWithFlags(&eKw, cudaEventDisableTiming);
        cudaEventCreateWithFlags(&eKdone, cudaEventDisableTiming);
        cudaEventCreateWithFlags(&eVdone, cudaEventDisableTiming);
        cudaEventCreateWithFlags(&eOw, cudaEventDisableTiming);
        cudaEventCreateWithFlags(&eQ2, cudaEventDisableTiming);
        cudaEventCreateWithFlags(&eF1, cudaEventDisableTiming);
        cudaEventCreateWithFlags(&eOg1, cudaEventDisableTiming);
        cfg = 1;
    }

    const long long kvBS = (long long)S_LEN * K_HEADS * H_DIM;
    const long long pHS = (long long)D_DIM * H_DIM;

    // FORK
    cudaEventRecord(eFork, 0);
    cudaStreamWaitEvent(s1, eFork, 0);
    cudaStreamWaitEvent(s2, eFork, 0);

    // s0: hs convert
    a2h_kernel<<<(4096LL * 2048) / 1024, 256, 0, 0>>>(hs, hs2);
    cudaEventRecord(eHs, 0);
    // s1: enc convert
    a2h_kernel<<<(4096LL * 2048) / 1024, 256, 0, s1>>>(enc, enc2);
    cudaEventRecord(eEnc, s1);
    // s2: weight converts
    wsplit_kernel<<<dim3(4096 / 32, D_DIM / 32), 256, 0, s2>>>(qw, qw2, D_DIM, H_DIM, pHS, H_DIM);
    cudaEventRecord(eQw, s2);
    wsplit_kernel<<<dim3(2048 / 32, D_DIM / 32), 256, 0, s2>>>(kw, kw2, D_DIM, H_DIM, pHS, H_DIM);
    cudaEventRecord(eKw, s2);
    wsplit_kernel<<<dim3(2048 / 32, D_DIM / 32), 256, 0, s2>>>(vw, vw2, D_DIM, H_DIM, pHS, H_DIM);

    // s0: Q first half (rows t<512 per batch) + rms
    cudaStreamWaitEvent(0, eQw, 0);
    gemm_hmma<<<dim3(32, 16), 128, GEMM_SMEM, 0>>>(hs2, qw2, qb, 2048, 4096, 0LL, 0, 4096, 0, 4, 1024, 0);
    rms_rope_w_kernel<<<B_SZ * 512 * N_HEADS / 8, 256, 0, 0>>>(qb, q16, qsc, N_HEADS, 512, T_LEN, 0, 1, 0.0625f);

    // s1: K path, then Q second half (overlaps flash half 1)
    cudaStreamWaitEvent(s1, eHs, 0);
    cudaStreamWaitEvent(s1, eKw, 0);
    gemm_hmma<<<dim3(16, 32), 128, GEMM_SMEM, s1>>>(hs2, kw2, kb, 2048, T_LEN, kvBS, 0, 2048, 0, 32, 0, 0);
    gemm_hmma<<<dim3(16, 32), 128, GEMM_SMEM, s1>>>(enc2, kw2, kb, 2048, E_LEN, kvBS, T_LEN, 2048, 0, 32, 0, 0);
    rms_rope_w_kernel<<<B_SZ * T_LEN * K_HEADS / 8, 256, 0, s1>>>(kb, k16, ksc, K_HEADS, T_LEN, S_LEN, 0, 1, 1.0f);
    rms_rope_w_kernel<<<B_SZ * E_LEN * K_HEADS / 8, 256, 0, s1>>>(kb, k16, ksc, K_HEADS, E_LEN, S_LEN, T_LEN, 0, 1.0f);
    cudaEventRecord(eKdone, s1);
    gemm_hmma<<<dim3(32, 16), 128, GEMM_SMEM, s1>>>(hs2, qw2, qb, 2048, 4096, 0LL, 0, 4096, 0, 4, 1024, 512);
    rms_rope_w_kernel<<<B_SZ * 512 * N_HEADS / 8, 256, 0, s1>>>(qb, q16, qsc, N_HEADS, 512, T_LEN, 512, 1, 0.0625f);
    cudaEventRecord(eQ2, s1);

    // s2: V path + ow convert
    cudaStreamWaitEvent(s2, eHs, 0);
    cudaStreamWaitEvent(s2, eEnc, 0);
    gemm_hmma<<<dim3(16, 32), 128, GEMM_SMEM, s2>>>(hs2, vw2, v16, 2048, T_LEN, kvBS, 0, 2048, 1, 32, 0, 0);
    gemm_hmma<<<dim3(16, 32), 128, GEMM_SMEM, s2>>>(enc2, vw2, v16, 2048, E_LEN, kvBS, T_LEN, 2048, 1, 32, 0, 0);
    cudaEventRecord(eVdone, s2);
    wsplit_kernel<<<dim3(2048 / 32, 4096 / 32), 256, 0, s2>>>(ow, ow2, 4096, D_DIM, 0LL, D_DIM);
    cudaEventRecord(eOw, s2);

    // s0: flash half 1 (qt 0..3, needs q16 t<512 + K + V)
    cudaStreamWaitEvent(0, eKdone, 0);
    cudaStreamWaitEvent(0, eVdone, 0);
    flash2_hmma<<<dim3(4, N_HEADS, B_SZ), 256, FH2_SMEM, 0>>>(q16, k16, v16, at2, 0);
    cudaEventRecord(eF1, 0);
    // s0: flash half 2 (qt 4..7, needs q16 t>=512)
    cudaStreamWaitEvent(0, eQ2, 0);
    flash2_hmma<<<dim3(4, N_HEADS, B_SZ), 256, FH2_SMEM, 0>>>(q16, k16, v16, at2, 4);

    // s1: O-GEMM half 1 (rows t<512) overlaps flash half 2
    cudaStreamWaitEvent(s1, eF1, 0);
    cudaStreamWaitEvent(s1, eOw, 0);
    gemm_hmma<<<dim3(16, 16), 128, GEMM_SMEM, s1>>>(at2, ow2, out, 4096, 4096, 0LL, 0, 2048, 0, 4, 1024, 0);
    cudaEventRecord(eOg1, s1);

    // s0: O-GEMM half 2 (rows t>=512), join all
    cudaStreamWaitEvent(0, eOw, 0);
    cudaStreamWaitEvent(0, eOg1, 0);
    gemm_hmma<<<dim3(16, 16), 128, GEMM_SMEM, 0>>>(at2, ow2, out, 4096, 4096, 0LL, 0, 2048, 0, 4, 1024, 512);
}

// round 17
// speedup vs baseline: 1.0260x; 1.0074x over previous
#include <cuda_runtime.h>
#include <cuda_fp16.h>
#include <stdint.h>
#include <math.h>

#define B_SZ 4
#define T_LEN 1024
#define E_LEN 1024
#define S_LEN 2048
#define D_DIM 2048
#define H_DIM 256
#define N_HEADS 16
#define K_HEADS 8

__device__ float g_q[(size_t)B_SZ * T_LEN * N_HEADS * H_DIM];
__device__ float g_k[(size_t)B_SZ * S_LEN * K_HEADS * H_DIM];
__device__ __half g_q16[(size_t)B_SZ * T_LEN * N_HEADS * H_DIM];
__device__ __half g_k16[(size_t)B_SZ * S_LEN * K_HEADS * H_DIM];
__device__ __half g_v16[(size_t)B_SZ * S_LEN * K_HEADS * H_DIM];
__device__ __half g_hs2 [(size_t)4096 * 2048];
__device__ __half g_enc2[(size_t)4096 * 2048];
__device__ __half g_qw2 [(size_t)4096 * 2048];
__device__ __half g_kw2 [(size_t)2048 * 2048];
__device__ __half g_vw2 [(size_t)2048 * 2048];
__device__ __half g_ow2 [(size_t)2048 * 4096];
__device__ __half g_at2 [(size_t)4096 * 4096];

// ---------------- helpers ----------------
__device__ __forceinline__ uint32_t smem_u32(const void* p) {
    uint32_t a;
    asm("{ .reg .u64 t; cvta.to.shared.u64 t, %1; cvt.u32.u64 %0, t; }" : "=r"(a) : "l"(p));
    return a;
}
#define CP16(dst, src) \
    asm volatile("cp.async.cg.shared.global [%0], [%1], 16;" :: "r"(dst), "l"(src) : "memory")
#define CP_COMMIT asm volatile("cp.async.commit_group;" ::: "memory")
#define CP_WAIT2  asm volatile("cp.async.wait_group 2;" ::: "memory")
#define CP_WAIT1  asm volatile("cp.async.wait_group 1;" ::: "memory")
#define CP_WAIT0  asm volatile("cp.async.wait_group 0;" ::: "memory")
#define LDSM4(r0, r1, r2, r3, addr) \
    asm volatile("ldmatrix.sync.aligned.m8n8.x4.shared.b16 {%0,%1,%2,%3}, [%4];" \
        : "=r"(r0), "=r"(r1), "=r"(r2), "=r"(r3) : "r"(addr))
#define LDSM4T(r0, r1, r2, r3, addr) \
    asm volatile("ldmatrix.sync.aligned.m8n8.x4.trans.shared.b16 {%0,%1,%2,%3}, [%4];" \
        : "=r"(r0), "=r"(r1), "=r"(r2), "=r"(r3) : "r"(addr))
#define MMAH16816(d, a, b0, b1) \
    asm volatile("mma.sync.aligned.m16n8k16.row.col.f32.f16.f16.f32 " \
        "{%0,%1,%2,%3}, {%4,%5,%6,%7}, {%8,%9}, {%0,%1,%2,%3};" \
        : "+f"((d)[0]), "+f"((d)[1]), "+f"((d)[2]), "+f"((d)[3]) \
        : "r"((a)[0]), "r"((a)[1]), "r"((a)[2]), "r"((a)[3]), "r"(b0), "r"(b1))

__device__ __forceinline__ uint32_t gsw(int row, int kchunk) {
    return (uint32_t)(row * 128 + ((kchunk ^ (row & 7)) << 4));
}
__device__ __forceinline__ uint32_t fsw(int row, int kbyte) {
    return (uint32_t)(row * 512 + ((((kbyte >> 4) ^ (row & 7))) << 4) + (kbyte & 15));
}
__device__ __forceinline__ uint32_t packh2(float a, float b) {
    __half2 h = __floats2half2_rn(a, b);
    return *(uint32_t*)&h;
}

// ---------------- convert kernels ----------------
__global__ __launch_bounds__(256) void a2h_kernel(
    const float* __restrict__ X, __half* __restrict__ Y)
{
    size_t idx = ((size_t)blockIdx.x * 256 + threadIdx.x) * 4;
    float4 v = *(const float4*)(X + idx);
    __half2 h0 = __floats2half2_rn(v.x, v.y);
    __half2 h1 = __floats2half2_rn(v.z, v.w);
    *(uint2*)(Y + idx) = make_uint2(*(uint32_t*)&h0, *(uint32_t*)&h1);
}

__global__ __launch_bounds__(256) void wsplit_kernel(
    const float* __restrict__ W, __half* __restrict__ Yt,
    int Kd, int cph, long long hstr, int krs)
{
    __shared__ float t[32][33];
    int k0 = blockIdx.y * 32, j0 = blockIdx.x * 32;
    int tx = threadIdx.x & 31, ty8 = threadIdx.x >> 5;
#pragma unroll
    for (int i = 0; i < 4; i++) {
        int kl = ty8 + i * 8;
        int j = j0 + tx;
        t[kl][tx] = W[(size_t)(j / cph) * hstr + (size_t)(k0 + kl) * krs + (j % cph)];
    }
    __syncthreads();
#pragma unroll
    for (int i = 0; i < 4; i++) {
        int j = j0 + ty8 + i * 8;
        int k = k0 + tx;
        Yt[(size_t)j * Kd + k] = __float2half(t[tx][ty8 + i * 8]);
    }
}

// ---------------- HMMA fp16 GEMM (unchanged) ----------------
#define GSTAGES 3
#define STG_BYTES 32768
#define GEMM_SMEM (GSTAGES * STG_BYTES)

__global__ void __launch_bounds__(128, 2) gemm_hmma(
    const __half* __restrict__ A, const __half* __restrict__ Bw,
    void* __restrict__ Cv, int Kp, int Mpb, long long outBS, int rowOff, int ldc,
    int outHalf, int mGT, int mGS, int mOff)
{
    extern __shared__ char smraw[];
    const uint32_t sb = smem_u32(smraw);
    const int tid = threadIdx.x;
    const int lane = tid & 31, wid = tid >> 5;
    const int wm = wid & 1, wn = wid >> 1;
    const int m0 = (blockIdx.y / mGT) * mGS + (blockIdx.y % mGT) * 128 + mOff;
    const int n0 = blockIdx.x * 128;
    const int nIter = Kp >> 6;

    const int crow = tid >> 3;
    const int ckc = tid & 7;
    const uint32_t csw = gsw(crow, ckc);
    const __half* ga = A + (size_t)(m0 + crow) * Kp + ckc * 8;
    const __half* gb = Bw + (size_t)(n0 + crow) * Kp + ckc * 8;

    const int r8 = lane & 7, sel = lane >> 3;
    uint32_t aRB[4]; int aRX[4];
    const int dselA = sel >> 1;
#pragma unroll
    for (int mf = 0; mf < 4; mf++) {
        int row = wm * 64 + mf * 16 + r8 + ((sel & 1) << 3);
        aRB[mf] = (uint32_t)(row * 128);
        aRX[mf] = row & 7;
    }
    uint32_t bRB[4]; int bRX[4];
    const int dselB = sel & 1;
#pragma unroll
    for (int np = 0; np < 4; np++) {
        int row = wn * 64 + np * 16 + r8 + ((sel >> 1) << 3);
        bRB[np] = 16384u + (uint32_t)(row * 128);
        bRX[np] = row & 7;
    }

    float acc[4][8][4];
#pragma unroll
    for (int mf = 0; mf < 4; mf++)
#pragma unroll
        for (int nf = 0; nf < 8; nf++)
#pragma unroll
            for (int q = 0; q < 4; q++) acc[mf][nf][q] = 0.f;

#pragma unroll
    for (int s = 0; s < 2; s++) {
        uint32_t base = sb + (uint32_t)s * STG_BYTES;
        const __half* pa = ga + s * 64;
        const __half* pb = gb + s * 64;
#pragma unroll
        for (int p = 0; p < 8; p++) {
            uint32_t so = csw + (uint32_t)p * 2048u;
            CP16(base + so, pa + (size_t)p * 16 * Kp);
            CP16(base + 16384u + so, pb + (size_t)p * 16 * Kp);
        }
        CP_COMMIT;
    }

    for (int it = 0; it < nIter; it++) {
        if (it + 2 < nIter) {
            int s = (it + 2) % GSTAGES;
            uint32_t base = sb + (uint32_t)s * STG_BYTES;
            const __half* pa = ga + (size_t)(it + 2) * 64;
            const __half* pb = gb + (size_t)(it + 2) * 64;
#pragma unroll
            for (int p = 0; p < 8; p++) {
                uint32_t so = csw + (uint32_t)p * 2048u;
                CP16(base + so, pa + (size_t)p * 16 * Kp);
                CP16(base + 16384u + so, pb + (size_t)p * 16 * Kp);
            }
        }
        CP_COMMIT;
        CP_WAIT2;
        __syncthreads();

        uint32_t sbase = sb + (uint32_t)(it % GSTAGES) * STG_BYTES;
#pragma unroll
        for (int ks = 0; ks < 4; ks++) {
            uint32_t af[4][4];
#pragma unroll
            for (int mf = 0; mf < 4; mf++)
                LDSM4(af[mf][0], af[mf][1], af[mf][2], af[mf][3],
                      sbase + aRB[mf] + (uint32_t)((((ks << 1) + dselA) ^ aRX[mf]) << 4));
            uint32_t bf[4][4];
#pragma unroll
            for (int np = 0; np < 4; np++)
                LDSM4(bf[np][0], bf[np][1], bf[np][2], bf[np][3],
                      sbase + bRB[np] + (uint32_t)((((ks << 1) + dselB) ^ bRX[np]) << 4));
#pragma unroll
            for (int mf = 0; mf < 4; mf++)
#pragma unroll
                for (int np = 0; np < 4; np++) {
                    MMAH16816(acc[mf][np * 2 + 0], af[mf], bf[np][0], bf[np][1]);
                    MMAH16816(acc[mf][np * 2 + 1], af[mf], bf[np][2], bf[np][3]);
                }
        }
        __syncthreads();
    }

#pragma unroll
    for (int mf = 0; mf < 4; mf++)
#pragma unroll
        for (int rh = 0; rh < 2; rh++) {
            int gr = m0 + wm * 64 + mf * 16 + (lane >> 2) + rh * 8;
            int bi = gr / Mpb;
            int rr = gr - bi * Mpb;
            size_t base = (size_t)bi * outBS + (size_t)(rr + rowOff) * ldc
                        + n0 + wn * 64 + (lane & 3) * 2;
            if (outHalf) {
                __half* rowp = (__half*)Cv + base;
#pragma unroll
                for (int nf = 0; nf < 8; nf++) {
                    __half2 v = __floats2half2_rn(acc[mf][nf][rh * 2 + 0], acc[mf][nf][rh * 2 + 1]);
                    *(__half2*)(rowp + nf * 8) = v;
                }
            } else {
                float* rowp = (float*)Cv + base;
#pragma unroll
                for (int nf = 0; nf < 8; nf++) {
                    float2 v = make_float2(acc[mf][nf][rh * 2 + 0], acc[mf][nf][rh * 2 + 1]);
                    *(float2*)(rowp + nf * 8) = v;
                }
            }
        }
}

// ---------------- RMS-norm (+RoPE) fp32 -> fp16, warp-per-row ----------------
__global__ __launch_bounds__(256) void rms_rope_w_kernel(
    const float* __restrict__ buf, __half* __restrict__ outh,
    const float* __restrict__ scale,
    int heads, int rowsPerBatch, int bufRPB, int rowStart, int doRope, float outScale)
{
    int rowIdx = blockIdx.x * 8 + (threadIdx.x >> 5);
    int lane = threadIdx.x & 31;
    int head = rowIdx % heads;
    int tmp = rowIdx / heads;
    int t = tmp % rowsPerBatch;
    int b = tmp / rowsPerBatch;
    size_t off = ((size_t)((size_t)b * bufRPB + rowStart + t) * heads + head) * H_DIM;

    float4 x1 = *(const float4*)(buf + off + lane * 4);
    float4 x2 = *(const float4*)(buf + off + 128 + lane * 4);
    float ss = x1.x * x1.x + x1.y * x1.y + x1.z * x1.z + x1.w * x1.w
             + x2.x * x2.x + x2.y * x2.y + x2.z * x2.z + x2.w * x2.w;
#pragma unroll
    for (int o = 16; o > 0; o >>= 1) ss += __shfl_xor_sync(0xffffffffu, ss, o);
    float rinv = rsqrtf(ss * (1.f / 256.f) + 1e-6f) * outScale;

    float4 s1 = *(const float4*)(scale + lane * 4);
    float4 s2 = *(const float4*)(scale + 128 + lane * 4);
    float y1[4] = { x1.x * rinv * (1.f + s1.x), x1.y * rinv * (1.f + s1.y),
                    x1.z * rinv * (1.f + s1.z), x1.w * rinv * (1.f + s1.w) };
    float y2[4] = { x2.x * rinv * (1.f + s2.x), x2.y * rinv * (1.f + s2.y),
                    x2.z * rinv * (1.f + s2.z), x2.w * rinv * (1.f + s2.w) };
    float o1[4], o2[4];
    if (doRope) {
        float pos = (float)(rowStart + t);
#pragma unroll
        for (int i = 0; i < 4; i++) {
            float ang = pos * exp2f(-(float)(lane * 4 + i) * 0.10381025296522988f);
            float sn, cs;
            sincosf(ang, &sn, &cs);
            o1[i] = y1[i] * cs - y2[i] * sn;
            o2[i] = y2[i] * cs + y1[i] * sn;
        }
    } else {
#pragma unroll
        for (int i = 0; i < 4; i++) { o1[i] = y1[i]; o2[i] = y2[i]; }
    }
    __half2 a0 = __floats2half2_rn(o1[0], o1[1]);
    __half2 a1 = __floats2half2_rn(o1[2], o1[3]);
    __half2 b0 = __floats2half2_rn(o2[0], o2[1]);
    __half2 b1 = __floats2half2_rn(o2[2], o2[3]);
    *(uint2*)(outh + off + lane * 4) = make_uint2(*(uint32_t*)&a0, *(uint32_t*)&a1);
    *(uint2*)(outh + off + 128 + lane * 4) = make_uint2(*(uint32_t*)&b0, *(uint32_t*)&b1);
}

// ---------------- flash v3 (unchanged) ----------------
#define F2_KB 65536u
#define F2_VB 131072u
#define F2_ST 32768u
#define FH2_SMEM 196608

__global__ void __launch_bounds__(256, 1) flash2_hmma(
    const __half* __restrict__ Qh, const __half* __restrict__ Kh,
    const __half* __restrict__ Vh, __half* __restrict__ Oh, int qt0)
{
    extern __shared__ char smraw[];
    const uint32_t sb = smem_u32(smraw);
    const int tid = threadIdx.x, lane = tid & 31, w = tid >> 5;
    const int qt = blockIdx.x + qt0, n = blockIdx.y, b = blockIdx.z;
    const int kh = n >> 1, qbase = qt << 7;

    const char* qg = (const char*)(Qh + ((size_t)(b * T_LEN + qbase) * N_HEADS + n) * H_DIM);
#pragma unroll
    for (int p = 0; p < 16; p++) {
        int idx = tid + p * 256;
        int r = idx >> 5, c = idx & 31;
        CP16(sb + fsw(r, c * 16), qg + (size_t)r * (N_HEADS * H_DIM * 2) + c * 16);
    }
    CP_COMMIT;

    const char* kg = (const char*)(Kh + ((size_t)b * S_LEN * K_HEADS + kh) * H_DIM);
    const char* vg = (const char*)(Vh + ((size_t)b * S_LEN * K_HEADS + kh) * H_DIM);
    const int kvstride = K_HEADS * H_DIM * 2;

    const int nSelf = (qt + 1) << 1;
    const int nT = nSelf + (E_LEN >> 6);

#pragma unroll
    for (int p = 0; p < 8; p++) {
        int idx = tid + p * 256;
        int r = idx >> 5, c = idx & 31;
        uint32_t sw = fsw(r, c * 16);
        CP16(sb + F2_KB + sw, kg + (size_t)r * kvstride + c * 16);
        CP16(sb + F2_VB + sw, vg + (size_t)r * kvstride + c * 16);
    }
    CP_COMMIT;

    float oacc[32][4];
#pragma unroll
    for (int nf = 0; nf < 32; nf++)
#pragma unroll
        for (int q = 0; q < 4; q++) oacc[nf][q] = 0.f;
    float m1 = -INFINITY, m2 = -INFINITY, l1 = 0.f, l2 = 0.f;

    const int r8 = lane & 7, sel = lane >> 3;
    const int rowA = w * 16 + r8 + ((sel & 1) << 3);
    const int dselA = sel >> 1;
    const int dselB = sel & 1;
    const int r1g = w * 16 + (lane >> 2), r2g = r1g + 8;
    const uint32_t aBaseQ = sb + (uint32_t)rowA * 512u;
    const int rowAx = rowA & 7;

    for (int t = 0; t < nT; t++) {
        if (t + 1 < nT) {
            int s0n = (t + 1 < nSelf) ? ((t + 1) << 6) : (T_LEN + ((t + 1 - nSelf) << 6));
            uint32_t kb = sb + F2_KB + (uint32_t)((t + 1) & 1) * F2_ST;
            uint32_t vb = sb + F2_VB + (uint32_t)((t + 1) & 1) * F2_ST;
#pragma unroll
            for (int p = 0; p < 8; p++) {
                int idx = tid + p * 256;
                int r = idx >> 5, c = idx & 31;
                uint32_t sw = fsw(r, c * 16);
                CP16(kb + sw, kg + (size_t)(s0n + r) * kvstride + c * 16);
                CP16(vb + sw, vg + (size_t)(s0n + r) * kvstride + c * 16);
            }
            CP_COMMIT;
            CP_WAIT1;
        } else {
            CP_WAIT0;
        }
        __syncthreads();

        const int s0 = (t < nSelf) ? (t << 6) : (T_LEN + ((t - nSelf) << 6));
        const bool diag = (t >= nSelf - 2) && (t < nSelf);
        const uint32_t sK = sb + F2_KB + (uint32_t)(t & 1) * F2_ST;
        const uint32_t sV = sb + F2_VB + (uint32_t)(t & 1) * F2_ST;

        float sacc[8][4];
#pragma unroll
        for (int nf = 0; nf < 8; nf++)
#pragma unroll
            for (int q = 0; q < 4; q++) sacc[nf][q] = 0.f;
#pragma unroll 4
        for (int ks = 0; ks < 16; ks++) {
            uint32_t a[4];
            LDSM4(a[0], a[1], a[2], a[3], aBaseQ + (uint32_t)((((ks << 1) + dselA) ^ rowAx) << 4));
#pragma unroll
            for (int nf2 = 0; nf2 < 4; nf2++) {
                int rowB = nf2 * 16 + r8 + ((sel >> 1) << 3);
                uint32_t bb[4];
                LDSM4(bb[0], bb[1], bb[2], bb[3],
                      sK + (uint32_t)rowB * 512u + (uint32_t)((((ks << 1) + dselB) ^ (rowB & 7)) << 4));
                MMAH16816(sacc[nf2 * 2 + 0], a, bb[0], bb[1]);
                MMAH16816(sacc[nf2 * 2 + 1], a, bb[2], bb[3]);
            }
        }

        float mx1 = -INFINITY, mx2 = -INFINITY;
#pragma unroll
        for (int nf = 0; nf < 8; nf++)
#pragma unroll
            for (int e = 0; e < 4; e++) {
                float s = sacc[nf][e];
                float cpv = 50.f - __fdividef(100.f, __expf(0.04f * s) + 1.f);
                if (diag) {
                    int col = s0 + nf * 8 + ((lane & 3) << 1) + (e & 1);
                    int row = qbase + ((e < 2) ? r1g : r2g);
                    if (col > row) cpv = -INFINITY;
                }
                sacc[nf][e] = cpv;
                if (e < 2) mx1 = fmaxf(mx1, cpv); else mx2 = fmaxf(mx2, cpv);
            }
        mx1 = fmaxf(mx1, __shfl_xor_sync(0xffffffffu, mx1, 1));
        mx1 = fmaxf(mx1, __shfl_xor_sync(0xffffffffu, mx1, 2));
        mx2 = fmaxf(mx2, __shfl_xor_sync(0xffffffffu, mx2, 1));
        mx2 = fmaxf(mx2, __shfl_xor_sync(0xffffffffu, mx2, 2));
        float mn1 = fmaxf(m1, mx1), mn2 = fmaxf(m2, mx2);
        float corr1 = __expf(m1 - mn1), corr2 = __expf(m2 - mn2);
        m1 = mn1; m2 = mn2;

        uint32_t pfrag[4][4];
        float sum1 = 0.f, sum2 = 0.f;
#pragma unroll
        for (int nf = 0; nf < 8; nf++) {
            float p0 = __expf(sacc[nf][0] - mn1);
            float p1 = __expf(sacc[nf][1] - mn1);
            float p2 = __expf(sacc[nf][2] - mn2);
            float p3 = __expf(sacc[nf][3] - mn2);
            sum1 += p0 + p1; sum2 += p2 + p3;
            int ks = nf >> 1, hi = nf & 1;
            pfrag[ks][hi * 2 + 0] = packh2(p0, p1);
            pfrag[ks][hi * 2 + 1] = packh2(p2, p3);
        }
        sum1 += __shfl_xor_sync(0xffffffffu, sum1, 1);
        sum1 += __shfl_xor_sync(0xffffffffu, sum1, 2);
        sum2 += __shfl_xor_sync(0xffffffffu, sum2, 1);
        sum2 += __shfl_xor_sync(0xffffffffu, sum2, 2);
        l1 = l1 * corr1 + sum1;
        l2 = l2 * corr2 + sum2;

#pragma unroll
        for (int nf = 0; nf < 32; nf++) {
            oacc[nf][0] *= corr1; oacc[nf][1] *= corr1;
            oacc[nf][2] *= corr2; oacc[nf][3] *= corr2;
        }

#pragma unroll
        for (int ks = 0; ks < 4; ks++) {
            int rowV = ks * 16 + r8 + ((sel & 1) << 3);
            uint32_t vBase = sV + (uint32_t)rowV * 512u;
            int rVx = rowV & 7;
#pragma unroll
            for (int nf2 = 0; nf2 < 16; nf2++) {
                int chunk = nf2 * 2 + (sel >> 1);
                uint32_t bb[4];
                LDSM4T(bb[0], bb[1], bb[2], bb[3], vBase + (uint32_t)((chunk ^ rVx) << 4));
                MMAH16816(oacc[nf2 * 2 + 0], pfrag[ks], bb[0], bb[1]);
                MMAH16816(oacc[nf2 * 2 + 1], pfrag[ks], bb[2], bb[3]);
            }
        }
        __syncthreads();
    }

    float inv1 = 1.f / l1;
    float inv2 = 1.f / l2;
    int t1 = qbase + r1g, t2 = qbase + r2g;
    __half* o1 = Oh + ((size_t)(b * T_LEN + t1)) * (N_HEADS * H_DIM) + n * H_DIM + ((lane & 3) << 1);
    __half* o2 = Oh + ((size_t)(b * T_LEN + t2)) * (N_HEADS * H_DIM) + n * H_DIM + ((lane & 3) << 1);
#pragma unroll
    for (int nf = 0; nf < 32; nf++) {
        __half2 v1 = __floats2half2_rn(oacc[nf][0] * inv1, oacc[nf][1] * inv1);
        __half2 v2 = __floats2half2_rn(oacc[nf][2] * inv2, oacc[nf][3] * inv2);
        *(__half2*)(o1 + nf * 8) = v1;
        *(__half2*)(o2 + nf * 8) = v2;
    }
}

// ---------------- launch: fine-grained DAG ----------------
extern "C" void kernel_launch(void* const* d_in, const int* in_sizes, int n_in,
                              void* d_out, int out_size)
{
    (void)in_sizes; (void)n_in; (void)out_size;
    const float* hs  = (const float*)d_in[0];
    const float* enc = (const float*)d_in[1];
    const float* qw  = (const float*)d_in[4];
    const float* kw  = (const float*)d_in[5];
    const float* vw  = (const float*)d_in[6];
    const float* ow  = (const float*)d_in[7];
    const float* qsc = (const float*)d_in[8];
    const float* ksc = (const float*)d_in[9];
    float* out = (float*)d_out;

    float *qb, *kb;
    cudaGetSymbolAddress((void**)&qb, g_q);
    cudaGetSymbolAddress((void**)&kb, g_k);
    __half *q16, *k16, *v16;
    cudaGetSymbolAddress((void**)&q16, g_q16);
    cudaGetSymbolAddress((void**)&k16, g_k16);
    cudaGetSymbolAddress((void**)&v16, g_v16);
    __half *hs2, *enc2, *qw2, *kw2, *vw2, *ow2, *at2;
    cudaGetSymbolAddress((void**)&hs2, g_hs2);
    cudaGetSymbolAddress((void**)&enc2, g_enc2);
    cudaGetSymbolAddress((void**)&qw2, g_qw2);
    cudaGetSymbolAddress((void**)&kw2, g_kw2);
    cudaGetSymbolAddress((void**)&vw2, g_vw2);
    cudaGetSymbolAddress((void**)&ow2, g_ow2);
    cudaGetSymbolAddress((void**)&at2, g_at2);

    static int cfg = 0;
    static cudaStream_t s1, s2;
    static cudaEvent_t eFork, eHs, eEnc, eQw, eKw, eK1, eKdone, eV1, eVdone, eOw, eQ2, eF1, eOg1;
    if (!cfg) {
        cudaFuncSetAttribute(gemm_hmma, cudaFuncAttributeMaxDynamicSharedMemorySize, GEMM_SMEM);
        cudaFuncSetAttribute(flash2_hmma, cudaFuncAttributeMaxDynamicSharedMemorySize, FH2_SMEM);
        cudaStreamCreateWithFlags(&s1, cudaStreamNonBlocking);
        cudaStreamCreateWithFlags(&s2, cudaStreamNonBlocking);
        cudaEventCreateWithFlags(&eFork, cudaEventDisableTiming);
        cudaEventCreateWithFlags(&eHs, cudaEventDisableTiming);
        cudaEventCreateWithFlags(&eEnc, cudaEventDisableTiming);
        cudaEventCreateWithFlags(&eQw, cudaEventDisableTiming);
        cudaEventCreateWithFlags(&eKw, cudaEventDisableTiming);
        cudaEventCreateWithFlags(&eK1, cudaEventDisableTiming);
        cudaEventCreateWithFlags(&eKdone, cudaEventDisableTiming);
        cudaEventCreateWithFlags(&eV1, cudaEventDisableTiming);
        cudaEventCreateWithFlags(&eVdone, cudaEventDisableTiming);
        cudaEventCreateWithFlags(&eOw, cudaEventDisableTiming);
        cudaEventCreateWithFlags(&eQ2, cudaEventDisableTiming);
        cudaEventCreateWithFlags(&eF1, cudaEventDisableTiming);
        cudaEventCreateWithFlags(&eOg1, cudaEventDisableTiming);
        cfg = 1;
    }

    const long long kvBS = (long long)S_LEN * K_HEADS * H_DIM;
    const long long pHS = (long long)D_DIM * H_DIM;

    // FORK
    cudaEventRecord(eFork, 0);
    cudaStreamWaitEvent(s1, eFork, 0);
    cudaStreamWaitEvent(s2, eFork, 0);

    // s0: hs convert
    a2h_kernel<<<(4096LL * 2048) / 1024, 256, 0, 0>>>(hs, hs2);
    cudaEventRecord(eHs, 0);
    // s1: enc convert
    a2h_kernel<<<(4096LL * 2048) / 1024, 256, 0, s1>>>(enc, enc2);
    cudaEventRecord(eEnc, s1);
    // s2: weight converts
    wsplit_kernel<<<dim3(4096 / 32, D_DIM / 32), 256, 0, s2>>>(qw, qw2, D_DIM, H_DIM, pHS, H_DIM);
    cudaEventRecord(eQw, s2);
    wsplit_kernel<<<dim3(2048 / 32, D_DIM / 32), 256, 0, s2>>>(kw, kw2, D_DIM, H_DIM, pHS, H_DIM);
    cudaEventRecord(eKw, s2);
    wsplit_kernel<<<dim3(2048 / 32, D_DIM / 32), 256, 0, s2>>>(vw, vw2, D_DIM, H_DIM, pHS, H_DIM);

    // s0: Q first half (rows t<512) + rms
    cudaStreamWaitEvent(0, eQw, 0);
    gemm_hmma<<<dim3(32, 16), 128, GEMM_SMEM, 0>>>(hs2, qw2, qb, 2048, 4096, 0LL, 0, 4096, 0, 4, 1024, 0);
    rms_rope_w_kernel<<<B_SZ * 512 * N_HEADS / 8, 256, 0, 0>>>(qb, q16, qsc, N_HEADS, 512, T_LEN, 0, 1, 0.0625f);

    // s1: K path (self-h1, cross -> eK1; self-h2 deferred)
    cudaStreamWaitEvent(s1, eHs, 0);
    cudaStreamWaitEvent(s1, eKw, 0);
    gemm_hmma<<<dim3(16, 16), 128, GEMM_SMEM, s1>>>(hs2, kw2, kb, 2048, T_LEN, kvBS, 0, 2048, 0, 4, 1024, 0);
    rms_rope_w_kernel<<<B_SZ * 512 * K_HEADS / 8, 256, 0, s1>>>(kb, k16, ksc, K_HEADS, 512, S_LEN, 0, 1, 1.0f);
    gemm_hmma<<<dim3(16, 32), 128, GEMM_SMEM, s1>>>(enc2, kw2, kb, 2048, E_LEN, kvBS, T_LEN, 2048, 0, 32, 0, 0);
    rms_rope_w_kernel<<<B_SZ * E_LEN * K_HEADS / 8, 256, 0, s1>>>(kb, k16, ksc, K_HEADS, E_LEN, S_LEN, T_LEN, 0, 1.0f);
    cudaEventRecord(eK1, s1);
    gemm_hmma<<<dim3(16, 16), 128, GEMM_SMEM, s1>>>(hs2, kw2, kb, 2048, T_LEN, kvBS, 0, 2048, 0, 4, 1024, 512);
    rms_rope_w_kernel<<<B_SZ * 512 * K_HEADS / 8, 256, 0, s1>>>(kb, k16, ksc, K_HEADS, 512, S_LEN, 512, 1, 1.0f);
    cudaEventRecord(eKdone, s1);

    // s2: V path (self-h1, cross -> eV1; self-h2 deferred), then Q-half2, ow
    cudaStreamWaitEvent(s2, eHs, 0);
    cudaStreamWaitEvent(s2, eEnc, 0);
    gemm_hmma<<<dim3(16, 16), 128, GEMM_SMEM, s2>>>(hs2, vw2, v16, 2048, T_LEN, kvBS, 0, 2048, 1, 4, 1024, 0);
    gemm_hmma<<<dim3(16, 32), 128, GEMM_SMEM, s2>>>(enc2, vw2, v16, 2048, E_LEN, kvBS, T_LEN, 2048, 1, 32, 0, 0);
    cudaEventRecord(eV1, s2);
    gemm_hmma<<<dim3(16, 16), 128, GEMM_SMEM, s2>>>(hs2, vw2, v16, 2048, T_LEN, kvBS, 0, 2048, 1, 4, 1024, 512);
    cudaEventRecord(eVdone, s2);
    gemm_hmma<<<dim3(32, 16), 128, GEMM_SMEM, s2>>>(hs2, qw2, qb, 2048, 4096, 0LL, 0, 4096, 0, 4, 1024, 512);
    rms_rope_w_kernel<<<B_SZ * 512 * N_HEADS / 8, 256, 0, s2>>>(qb, q16, qsc, N_HEADS, 512, T_LEN, 512, 1, 0.0625f);
    cudaEventRecord(eQ2, s2);
    wsplit_kernel<<<dim3(2048 / 32, 4096 / 32), 256, 0, s2>>>(ow, ow2, 4096, D_DIM, 0LL, D_DIM);
    cudaEventRecord(eOw, s2);

    // s0: flash half 1 (qt 0..3; needs Q t<512, K/V self t<512 + cross)
    cudaStreamWaitEvent(0, eK1, 0);
    cudaStreamWaitEvent(0, eV1, 0);
    flash2_hmma<<<dim3(4, N_HEADS, B_SZ), 256, FH2_SMEM, 0>>>(q16, k16, v16, at2, 0);
    cudaEventRecord(eF1, 0);
    // s0: flash half 2 (qt 4..7; needs everything)
    cudaStreamWaitEvent(0, eKdone, 0);
    cudaStreamWaitEvent(0, eVdone, 0);
    cudaStreamWaitEvent(0, eQ2, 0);
    flash2_hmma<<<dim3(4, N_HEADS, B_SZ), 256, FH2_SMEM, 0>>>(q16, k16, v16, at2, 4);

    // s1: O-GEMM half 1 (rows t<512) overlaps flash half 2
    cudaStreamWaitEvent(s1, eF1, 0);
    cudaStreamWaitEvent(s1, eOw, 0);
    gemm_hmma<<<dim3(16, 16), 128, GEMM_SMEM, s1>>>(at2, ow2, out, 4096, 4096, 0LL, 0, 2048, 0, 4, 1024, 0);
    cudaEventRecord(eOg1, s1);

    // s0: O-GEMM half 2 (rows t>=512), join all
    cudaStreamWaitEvent(0, eOw, 0);
    cudaStreamWaitEvent(0, eOg1, 0);
    gemm_hmma<<<dim3(16, 16), 128, GEMM_SMEM, 0>>>(at2, ow2, out, 4096, 4096, 0LL, 0, 2048, 0, 4, 1024, 512);
}